// round 11
// baseline (speedup 1.0000x reference)
#include <cuda_runtime.h>

#define BATCH   8192
#define INS     64
#define OUTS    64
#define NIP     (INS/2)        // 32 i-pairs
#define BROWS   128            // batch rows per block
#define RPT     4              // batch rows per lane (lane, lane+32, ...)

// Packed params: lanes of each f32x2 = (conn i, conn i+1). idx = ip*OUTS + o.
__device__ float4 g_P0[NIP * OUTS];  // (w1h0_i, w1h0_j, w1h1_i, w1h1_j)
__device__ float4 g_P1[NIP * OUTS];  // (b1h0_i, b1h0_j, b1h1_i, b1h1_j)
__device__ float4 g_P2[NIP * OUTS];  // (wA_i, wA_j, wB_i, wB_j)   [w2 k0]
__device__ float4 g_P3[NIP * OUTS];  // (wC_i, wC_j, wD_i, wD_j)   [w2 k1]
__device__ float4 g_P4[NIP * OUTS];  // (b2k0_i, b2k0_j, b2k1_i, b2k1_j)
__device__ float4 g_P5[NIP * OUTS];  // (w3k0_i, w3k0_j, w3k1_i, w3k1_j)
__device__ float2 g_B3[NIP * OUTS];  // (b3_i, b3_j)

// Packed f32x2 FMA (sm_103a — only reachable via PTX).
__device__ __forceinline__ float2 ffma2(float2 a, float2 b, float2 c) {
    float2 d;
    asm("{\n\t"
        ".reg .b64 ra, rb, rc, rd;\n\t"
        "mov.b64 ra, {%2, %3};\n\t"
        "mov.b64 rb, {%4, %5};\n\t"
        "mov.b64 rc, {%6, %7};\n\t"
        "fma.rn.f32x2 rd, ra, rb, rc;\n\t"
        "mov.b64 {%0, %1}, rd;\n\t"
        "}"
        : "=f"(d.x), "=f"(d.y)
        : "f"(a.x), "f"(a.y), "f"(b.x), "f"(b.y), "f"(c.x), "f"(c.y));
    return d;
}

__device__ __forceinline__ float2 relu2(float2 a) {
    a.x = fmaxf(a.x, 0.0f);
    a.y = fmaxf(a.y, 0.0f);
    return a;
}

__global__ void __launch_bounds__(256)
pack_kernel(const float2* __restrict__ w1, const float2* __restrict__ b1,
            const float4* __restrict__ w2, const float2* __restrict__ b2,
            const float2* __restrict__ w3, const float*  __restrict__ b3)
{
    const int t  = blockIdx.x * 256 + threadIdx.x;  // 0..2047
    const int ip = t >> 6;           // i-pair
    const int o  = t & (OUTS - 1);
    const int ci = (2 * ip) * OUTS + o;      // conn (2ip, o)
    const int cj = (2 * ip + 1) * OUTS + o;  // conn (2ip+1, o)

    const float2 W1i = w1[ci], W1j = w1[cj];
    const float2 B1i = b1[ci], B1j = b1[cj];
    const float4 W2i = w2[ci], W2j = w2[cj];
    const float2 B2i = b2[ci], B2j = b2[cj];
    const float2 W3i = w3[ci], W3j = w3[cj];

    g_P0[t] = make_float4(W1i.x, W1j.x, W1i.y, W1j.y);
    g_P1[t] = make_float4(B1i.x, B1j.x, B1i.y, B1j.y);
    g_P2[t] = make_float4(W2i.x, W2j.x, W2i.y, W2j.y);
    g_P3[t] = make_float4(W2i.z, W2j.z, W2i.w, W2j.w);
    g_P4[t] = make_float4(B2i.x, B2j.x, B2i.y, B2j.y);
    g_P5[t] = make_float4(W3i.x, W3j.x, W3i.y, W3j.y);
    g_B3[t] = make_float2(b3[ci], b3[cj]);
}

// Block: 256 thr = 8 warps. Warp ww owns ONE output column o = osec*8+ww,
// all 32 i-pairs, and 128 batch rows (lane + 32r). Params are lane-invariant
// -> every param LDG is a 1-wavefront broadcast. No cross-warp reduction.
__global__ void __launch_bounds__(256, 4)
kan_kernel(const float* __restrict__ x, float* __restrict__ out)
{
    __shared__ float2 xs2[NIP * BROWS];   // [ip][bb] : (x[b][2ip], x[b][2ip+1]), 32KB

    const int tid   = threadIdx.x;
    const int ww    = tid >> 5;
    const int lane  = tid & 31;
    const int btile = blockIdx.x >> 3;
    const int osec  = blockIdx.x & 7;
    const int b0    = btile * BROWS;
    const int o     = osec * 8 + ww;

    // Stage x pairs: xs2[ip][bb]. Each thread: one row-half (16 float2).
    {
        const int bb  = tid >> 1;            // 0..127
        const int ipg = (tid & 1) * 16;      // 0 or 16
        const float2* xrow = (const float2*)&x[(b0 + bb) * INS];
        #pragma unroll
        for (int kk = 0; kk < 16; kk++) {
            const int ip = ipg + kk;
            xs2[ip * BROWS + bb] = xrow[ip];
        }
    }
    __syncthreads();

    float2 acc[RPT];
    #pragma unroll
    for (int r = 0; r < RPT; r++) acc[r] = make_float2(0.0f, 0.0f);
    float2 sb3 = make_float2(0.0f, 0.0f);

    // Distance-1 prefetch for the first-consumed planes.
    float4 nP0 = __ldg(&g_P0[o]);
    float4 nP1 = __ldg(&g_P1[o]);

    #pragma unroll 2
    for (int ip = 0; ip < NIP; ip++) {
        const int idx = ip * OUTS + o;

        const float4 P0 = nP0;
        const float4 P1 = nP1;
        const int nidx = ((ip + 1) & (NIP - 1)) * OUTS + o;
        nP0 = __ldg(&g_P0[nidx]);
        nP1 = __ldg(&g_P1[nidx]);

        const float4 P2 = __ldg(&g_P2[idx]);
        const float4 P3 = __ldg(&g_P3[idx]);
        const float4 P4 = __ldg(&g_P4[idx]);
        const float4 P5 = __ldg(&g_P5[idx]);
        const float2 B3 = __ldg(&g_B3[idx]);
        sb3.x += B3.x;
        sb3.y += B3.y;

        // Aligned register pairs straight from LDG.128 — zero broadcast MOVs.
        const float2 w1a = make_float2(P0.x, P0.y), w1b = make_float2(P0.z, P0.w);
        const float2 b1a = make_float2(P1.x, P1.y), b1b = make_float2(P1.z, P1.w);
        const float2 wA  = make_float2(P2.x, P2.y), wB  = make_float2(P2.z, P2.w);
        const float2 wC  = make_float2(P3.x, P3.y), wD  = make_float2(P3.z, P3.w);
        const float2 b2a = make_float2(P4.x, P4.y), b2b = make_float2(P4.z, P4.w);
        const float2 w3a = make_float2(P5.x, P5.y), w3b = make_float2(P5.z, P5.w);

        const float2* xcol = &xs2[ip * BROWS + lane];

        #pragma unroll
        for (int r = 0; r < RPT; r++) {
            const float2 xv = xcol[32 * r];   // LDS.64, conflict-free
            float2 t0 = relu2(ffma2(xv, w1a, b1a));
            float2 t1 = relu2(ffma2(xv, w1b, b1b));
            float2 u0 = relu2(ffma2(t0, wA, ffma2(t1, wB, b2a)));
            float2 u1 = relu2(ffma2(t0, wC, ffma2(t1, wD, b2b)));
            acc[r] = ffma2(u0, w3a, ffma2(u1, w3b, acc[r]));
        }
    }

    // Collapse conn-pair lanes, fold b3 sum, write (scattered STG.32).
    const float sb = sb3.x + sb3.y;
    #pragma unroll
    for (int r = 0; r < RPT; r++)
        out[(b0 + lane + 32 * r) * OUTS + o] = (acc[r].x + acc[r].y) + sb;
}

extern "C" void kernel_launch(void* const* d_in, const int* in_sizes, int n_in,
                              void* d_out, int out_size)
{
    const float* x  = (const float*)d_in[0];
    const float* w1 = (const float*)d_in[1];
    const float* b1 = (const float*)d_in[2];
    const float* w2 = (const float*)d_in[3];
    const float* b2 = (const float*)d_in[4];
    const float* w3 = (const float*)d_in[5];
    const float* b3 = (const float*)d_in[6];
    float* out = (float*)d_out;

    pack_kernel<<<(NIP * OUTS) / 256, 256>>>(
        (const float2*)w1, (const float2*)b1, (const float4*)w2,
        (const float2*)b2, (const float2*)w3, b3);

    // 512 blocks: (8192/128 btiles) x (8 o-sections) — single wave.
    kan_kernel<<<(BATCH / BROWS) * 8, 256>>>(x, out);
}

// round 12
// speedup vs baseline: 1.5289x; 1.5289x over previous
#include <cuda_runtime.h>

#define BATCH   8192
#define INS     64
#define OUTS    64
#define NIP     (INS/2)        // 32 i-pairs
#define BTILE   8              // batch rows per block
#define QSPLIT  4              // i-pair split across warp groups
#define IPCHUNK (NIP/QSPLIT)   // 8 i-pairs per quarter

// Packed params: lanes of each f32x2 = (conn 2ip, conn 2ip+1). idx = ip*OUTS + o.
__device__ float4 g_P0[NIP * OUTS];  // (w1h0_i, w1h0_j, w1h1_i, w1h1_j)
__device__ float4 g_P1[NIP * OUTS];  // (b1h0_i, b1h0_j, b1h1_i, b1h1_j)
__device__ float4 g_P2[NIP * OUTS];  // (wA_i, wA_j, wB_i, wB_j)   [w2 k0]
__device__ float4 g_P3[NIP * OUTS];  // (wC_i, wC_j, wD_i, wD_j)   [w2 k1]
__device__ float4 g_P4[NIP * OUTS];  // (b2k0_i, b2k0_j, b2k1_i, b2k1_j)
__device__ float4 g_P5[NIP * OUTS];  // (w3k0_i, w3k0_j, w3k1_i, w3k1_j)
__device__ float  g_SB3[OUTS];       // sum_i b3[i][o]

// Packed f32x2 FMA (sm_103a — only reachable via PTX).
__device__ __forceinline__ float2 ffma2(float2 a, float2 b, float2 c) {
    float2 d;
    asm("{\n\t"
        ".reg .b64 ra, rb, rc, rd;\n\t"
        "mov.b64 ra, {%2, %3};\n\t"
        "mov.b64 rb, {%4, %5};\n\t"
        "mov.b64 rc, {%6, %7};\n\t"
        "fma.rn.f32x2 rd, ra, rb, rc;\n\t"
        "mov.b64 {%0, %1}, rd;\n\t"
        "}"
        : "=f"(d.x), "=f"(d.y)
        : "f"(a.x), "f"(a.y), "f"(b.x), "f"(b.y), "f"(c.x), "f"(c.y));
    return d;
}

__device__ __forceinline__ float2 relu2(float2 a) {
    a.x = fmaxf(a.x, 0.0f);
    a.y = fmaxf(a.y, 0.0f);
    return a;
}

__global__ void __launch_bounds__(256)
pack_kernel(const float2* __restrict__ w1, const float2* __restrict__ b1,
            const float4* __restrict__ w2, const float2* __restrict__ b2,
            const float2* __restrict__ w3, const float*  __restrict__ b3)
{
    const int t  = blockIdx.x * 256 + threadIdx.x;  // 0..2047
    const int ip = t >> 6;           // i-pair
    const int o  = t & (OUTS - 1);
    const int ci = (2 * ip) * OUTS + o;
    const int cj = (2 * ip + 1) * OUTS + o;

    const float2 W1i = w1[ci], W1j = w1[cj];
    const float2 B1i = b1[ci], B1j = b1[cj];
    const float4 W2i = w2[ci], W2j = w2[cj];
    const float2 B2i = b2[ci], B2j = b2[cj];
    const float2 W3i = w3[ci], W3j = w3[cj];

    g_P0[t] = make_float4(W1i.x, W1j.x, W1i.y, W1j.y);
    g_P1[t] = make_float4(B1i.x, B1j.x, B1i.y, B1j.y);
    g_P2[t] = make_float4(W2i.x, W2j.x, W2i.y, W2j.y);
    g_P3[t] = make_float4(W2i.z, W2j.z, W2i.w, W2j.w);
    g_P4[t] = make_float4(B2i.x, B2j.x, B2i.y, B2j.y);
    g_P5[t] = make_float4(W3i.x, W3j.x, W3i.y, W3j.y);

    // First 64 threads: per-o b3 sum (64 scalar loads each — trivial).
    if (t < OUTS) {
        float s = 0.0f;
        for (int i = 0; i < INS; i++) s += b3[i * OUTS + t];
        g_SB3[t] = s;
    }
}

__global__ void __launch_bounds__(256, 3)
kan_kernel(const float* __restrict__ x, float* __restrict__ out)
{
    __shared__ float xs[BTILE * INS];                 // xs[b*64 + i] (natural layout)
    __shared__ float part[QSPLIT * BTILE * OUTS];     // part[q][b][o]

    const int tid = threadIdx.x;
    const int o   = tid & (OUTS - 1);     // 0..63
    const int q   = tid >> 6;             // 0..3 : i-pair quarter
    const int b0  = blockIdx.x * BTILE;

    // Stage x tile: contiguous copy (global coalesced, smem linear).
    #pragma unroll
    for (int k = 0; k < (BTILE * INS) / 256; k++)
        xs[k * 256 + tid] = x[b0 * INS + k * 256 + tid];
    __syncthreads();

    float2 acc[BTILE];
    #pragma unroll
    for (int b = 0; b < BTILE; b++) acc[b] = make_float2(0.0f, 0.0f);

    const int ip_lo = q * IPCHUNK;
    const int base  = ip_lo * OUTS + o;

    // FULL distance-1 prefetch (all 6 planes) — R5's proven latency plan.
    float4 nP0 = __ldg(&g_P0[base]);
    float4 nP1 = __ldg(&g_P1[base]);
    float4 nP2 = __ldg(&g_P2[base]);
    float4 nP3 = __ldg(&g_P3[base]);
    float4 nP4 = __ldg(&g_P4[base]);
    float4 nP5 = __ldg(&g_P5[base]);

    #pragma unroll 4
    for (int k = 0; k < IPCHUNK; k++) {
        const float4 P0 = nP0, P1 = nP1, P2 = nP2;
        const float4 P3 = nP3, P4 = nP4, P5 = nP5;

        // prefetch next (wraps on last iter — harmless redundant load)
        const int nidx = base + ((k + 1) & (IPCHUNK - 1)) * OUTS;
        nP0 = __ldg(&g_P0[nidx]);
        nP1 = __ldg(&g_P1[nidx]);
        nP2 = __ldg(&g_P2[nidx]);
        nP3 = __ldg(&g_P3[nidx]);
        nP4 = __ldg(&g_P4[nidx]);
        nP5 = __ldg(&g_P5[nidx]);

        // Operands are aligned register pairs straight from LDG.128 — zero bcast MOVs.
        const float2 w1a = make_float2(P0.x, P0.y), w1b = make_float2(P0.z, P0.w);
        const float2 b1a = make_float2(P1.x, P1.y), b1b = make_float2(P1.z, P1.w);
        const float2 wA  = make_float2(P2.x, P2.y), wB  = make_float2(P2.z, P2.w);
        const float2 wC  = make_float2(P3.x, P3.y), wD  = make_float2(P3.z, P3.w);
        const float2 b2a = make_float2(P4.x, P4.y), b2b = make_float2(P4.z, P4.w);
        const float2 w3a = make_float2(P5.x, P5.y), w3b = make_float2(P5.z, P5.w);

        const int ip2 = 2 * (ip_lo + k);

        #pragma unroll
        for (int b = 0; b < BTILE; b++) {
            // lanes = (x[b][2ip], x[b][2ip+1]) : one broadcast LDS.64
            const float2 xv = *(const float2*)&xs[b * INS + ip2];
            float2 t0 = relu2(ffma2(xv, w1a, b1a));
            float2 t1 = relu2(ffma2(xv, w1b, b1b));
            float2 u0 = relu2(ffma2(t0, wA, ffma2(t1, wB, b2a)));
            float2 u1 = relu2(ffma2(t0, wC, ffma2(t1, wD, b2b)));
            acc[b] = ffma2(u0, w3a, ffma2(u1, w3b, acc[b]));
        }
    }

    // Collapse conn-pair lanes; write q-partials (b3 handled at final store).
    float* pq = &part[q * BTILE * OUTS];
    #pragma unroll
    for (int b = 0; b < BTILE; b++)
        pq[b * OUTS + o] = acc[b].x + acc[b].y;
    __syncthreads();

    // Reduce the four quarters + add per-o b3 sum; coalesced store.
    {
        const int f  = tid * 2;                // 0..510
        const int oo = f & (OUTS - 1);
        const float2* p2 = (const float2*)part;
        float2 a = p2[tid];
        float2 b = p2[256 + tid];
        float2 c = p2[512 + tid];
        float2 d = p2[768 + tid];
        float2 r;
        r.x = (a.x + b.x) + (c.x + d.x) + g_SB3[oo];
        r.y = (a.y + b.y) + (c.y + d.y) + g_SB3[oo + 1];
        *(float2*)&out[b0 * OUTS + f] = r;
    }
}

extern "C" void kernel_launch(void* const* d_in, const int* in_sizes, int n_in,
                              void* d_out, int out_size)
{
    const float* x  = (const float*)d_in[0];
    const float* w1 = (const float*)d_in[1];
    const float* b1 = (const float*)d_in[2];
    const float* w2 = (const float*)d_in[3];
    const float* b2 = (const float*)d_in[4];
    const float* w3 = (const float*)d_in[5];
    const float* b3 = (const float*)d_in[6];
    float* out = (float*)d_out;

    pack_kernel<<<(NIP * OUTS) / 256, 256>>>(
        (const float2*)w1, (const float2*)b1, (const float4*)w2,
        (const float2*)b2, (const float2*)w3, b3);

    kan_kernel<<<BATCH / BTILE, 256>>>(x, out);
}